// round 9
// baseline (speedup 1.0000x reference)
#include <cuda_runtime.h>
#include <cuda_fp16.h>

#define NNODES 100000
#define FEAT   128
#define HEADS  8
#define HC     64          // HEADS*CH
#define E0     1600000     // edges in edge_index (self loops handled analytically)
#define NB     391         // ceil(NNODES/256) scan blocks

// ---------------- scratch (device globals) ---------------------------------
__device__ __half2 g_hh[NNODES * 32];           // 12.8 MB: h in fp16 (messages only)
__device__ float g_asrc[NNODES * HEADS];        // 3.2 MB (fp32: feeds exp)
__device__ float g_adst[NNODES * HEADS];        // 3.2 MB
__device__ int   g_cnt[NNODES];                 // in-degree histogram
__device__ int   g_rowptr[NNODES + 1];          // CSR row pointers
__device__ int   g_rank[E0];                    // rank of edge within dst bucket
__device__ unsigned long long g_state[NB];      // lookback: flag<<32 | value
__device__ unsigned int g_ticket;               // dynamic block id
__device__ int   g_csr_src[E0];                 // CSR: src node per edge
__device__ int   g_is64;

// ---------------- K0: zero histogram + scan state + detect dtype -----------
// int64 values in [0, N) have every odd 32-bit word == 0 (little endian).
__global__ void init_kernel(const int* __restrict__ ei32) {
    int t = blockIdx.x * blockDim.x + threadIdx.x;
    if (t < NNODES) g_cnt[t] = 0;
    if (t < NB) g_state[t] = 0ull;
    if (t == 0) {
        g_ticket = 0u;
        int all_zero = 1;
#pragma unroll
        for (int i = 1; i < 16; i += 2) all_zero &= (ei32[i] == 0);
        g_is64 = all_zero;
    }
}

// ---------------- K1: histogram + per-edge bucket rank ---------------------
__global__ void hist_kernel(const void* __restrict__ ei) {
    int e = (blockIdx.x * blockDim.x + threadIdx.x) * 4;
    if (e >= E0) return;
    int d0, d1, d2, d3;
    if (g_is64) {
        longlong4 v = *(const longlong4*)((const long long*)ei + E0 + e);
        d0 = (int)v.x; d1 = (int)v.y; d2 = (int)v.z; d3 = (int)v.w;
    } else {
        int4 v = *(const int4*)((const int*)ei + E0 + e);
        d0 = v.x; d1 = v.y; d2 = v.z; d3 = v.w;
    }
    int r0 = atomicAdd(&g_cnt[d0], 1);
    int r1 = atomicAdd(&g_cnt[d1], 1);
    int r2 = atomicAdd(&g_cnt[d2], 1);
    int r3 = atomicAdd(&g_cnt[d3], 1);
    *(int4*)&g_rank[e] = make_int4(r0, r1, r2, r3);
}

// ---------------- K2: single-pass scan (decoupled lookback) ----------------
__global__ void scan_kernel() {
    __shared__ int sbid;
    __shared__ int wsum[8];
    __shared__ int stotal;
    __shared__ long long sprefix;

    int t = threadIdx.x;
    if (t == 0) sbid = atomicAdd(&g_ticket, 1u);
    __syncthreads();
    int bid = sbid;
    int i = bid * 256 + t;
    int lane = t & 31, w = t >> 5;

    int v = (i < NNODES) ? g_cnt[i] : 0;
    int x = v;
#pragma unroll
    for (int off = 1; off < 32; off <<= 1) {
        int y = __shfl_up_sync(0xFFFFFFFFu, x, off);
        if (lane >= off) x += y;
    }
    if (lane == 31) wsum[w] = x;
    __syncthreads();
    if (w == 0 && lane < 8) {
        int y = wsum[lane];
#pragma unroll
        for (int off = 1; off < 8; off <<= 1) {
            int z = __shfl_up_sync(0xFFu, y, off);
            if (lane >= off) y += z;
        }
        wsum[lane] = y;
    }
    __syncthreads();
    int incl = x + (w > 0 ? wsum[w - 1] : 0);
    if (t == 255) stotal = incl;
    __syncthreads();
    int total = stotal;

    if (t == 0) {
        if (bid == 0) {
            __threadfence();
            atomicExch(&g_state[0], (2ull << 32) | (unsigned int)total);
            sprefix = 0;
        } else {
            __threadfence();
            atomicExch(&g_state[bid], (1ull << 32) | (unsigned int)total);
            long long prefix = 0;
            int idx = bid - 1;
            while (true) {
                unsigned long long s = atomicAdd(&g_state[idx], 0ull);
                unsigned int flag = (unsigned int)(s >> 32);
                if (flag == 2u) { prefix += (unsigned int)s; break; }
                if (flag == 1u) { prefix += (unsigned int)s; idx--; }
            }
            sprefix = prefix;
            __threadfence();
            atomicExch(&g_state[bid], (2ull << 32) | (unsigned int)(prefix + total));
        }
        if (bid == 0) g_rowptr[NNODES] = E0;
    }
    __syncthreads();
    if (i < NNODES) g_rowptr[i] = (int)(sprefix + incl - v);
}

// ---------------- K3: scatter edges into CSR (atomic-free) -----------------
__global__ void scatter_kernel(const void* __restrict__ ei) {
    int e = (blockIdx.x * blockDim.x + threadIdx.x) * 4;
    if (e >= E0) return;
    int s0, s1, s2, s3, d0, d1, d2, d3;
    if (g_is64) {
        longlong4 sv = *(const longlong4*)((const long long*)ei + e);
        longlong4 dv = *(const longlong4*)((const long long*)ei + E0 + e);
        s0 = (int)sv.x; s1 = (int)sv.y; s2 = (int)sv.z; s3 = (int)sv.w;
        d0 = (int)dv.x; d1 = (int)dv.y; d2 = (int)dv.z; d3 = (int)dv.w;
    } else {
        int4 sv = *(const int4*)((const int*)ei + e);
        int4 dv = *(const int4*)((const int*)ei + E0 + e);
        s0 = sv.x; s1 = sv.y; s2 = sv.z; s3 = sv.w;
        d0 = dv.x; d1 = dv.y; d2 = dv.z; d3 = dv.w;
    }
    int4 rk = *(const int4*)&g_rank[e];
    g_csr_src[g_rowptr[d0] + rk.x] = s0;
    g_csr_src[g_rowptr[d1] + rk.y] = s1;
    g_csr_src[g_rowptr[d2] + rk.z] = s2;
    g_csr_src[g_rowptr[d3] + rk.w] = s3;
}

// ---------------- K4: h = x @ W + att-logit epilogue, h stored fp16 --------
// BM=128, BN=64, BK=32, 8x4 microtile, register prefetch.
// Logits computed from fp32 register accumulators (full precision into exp);
// only the linear message values h are quantized to fp16.
__global__ void gemm_kernel(const float* __restrict__ x, const float* __restrict__ W,
                            const float* __restrict__ att_src,
                            const float* __restrict__ att_dst) {
    __shared__ __align__(16) float Xs[32][132];    // [k][row] k-major
    __shared__ __align__(16) float Ws[32][64];

    int tid = threadIdx.x;
    int tx = tid & 15;                             // cols tx*4..+3
    int ty = tid >> 4;                             // rows ty*8..+7
    int rowBase = blockIdx.x * 128;

    float acc[8][4];
#pragma unroll
    for (int i = 0; i < 8; i++)
#pragma unroll
        for (int j = 0; j < 4; j++) acc[i][j] = 0.f;

    float4 xr[4], wr[2];
#pragma unroll
    for (int i = 0; i < 4; i++) {
        int idx = tid + i * 256;
        int r = idx >> 3, q = idx & 7;
        int grow = rowBase + r;
        xr[i] = (grow < NNODES)
              ? *(const float4*)(x + (size_t)grow * FEAT + q * 4)
              : make_float4(0.f, 0.f, 0.f, 0.f);
    }
#pragma unroll
    for (int i = 0; i < 2; i++) {
        int idx = tid + i * 256;
        int k = idx >> 4, q = idx & 15;
        wr[i] = *(const float4*)(W + (size_t)k * HC + q * 4);
    }

    for (int kt = 0; kt < 4; kt++) {
#pragma unroll
        for (int i = 0; i < 4; i++) {
            int idx = tid + i * 256;
            int r = idx >> 3, q = idx & 7;
            Xs[q * 4 + 0][r] = xr[i].x; Xs[q * 4 + 1][r] = xr[i].y;
            Xs[q * 4 + 2][r] = xr[i].z; Xs[q * 4 + 3][r] = xr[i].w;
        }
#pragma unroll
        for (int i = 0; i < 2; i++) {
            int idx = tid + i * 256;
            int k = idx >> 4, q = idx & 15;
            *(float4*)&Ws[k][q * 4] = wr[i];
        }
        __syncthreads();
        if (kt < 3) {
#pragma unroll
            for (int i = 0; i < 4; i++) {
                int idx = tid + i * 256;
                int r = idx >> 3, q = idx & 7;
                int grow = rowBase + r;
                xr[i] = (grow < NNODES)
                      ? *(const float4*)(x + (size_t)grow * FEAT + (kt + 1) * 32 + q * 4)
                      : make_float4(0.f, 0.f, 0.f, 0.f);
            }
#pragma unroll
            for (int i = 0; i < 2; i++) {
                int idx = tid + i * 256;
                int k = idx >> 4, q = idx & 15;
                wr[i] = *(const float4*)(W + (size_t)((kt + 1) * 32 + k) * HC + q * 4);
            }
        }
#pragma unroll
        for (int kk = 0; kk < 32; kk++) {
            float4 w4  = *(float4*)&Ws[kk][tx * 4];
            float4 xlo = *(float4*)&Xs[kk][ty * 8];
            float4 xhi = *(float4*)&Xs[kk][ty * 8 + 4];
            float xv[8] = {xlo.x, xlo.y, xlo.z, xlo.w, xhi.x, xhi.y, xhi.z, xhi.w};
#pragma unroll
            for (int i = 0; i < 8; i++) {
                acc[i][0] += xv[i] * w4.x;
                acc[i][1] += xv[i] * w4.y;
                acc[i][2] += xv[i] * w4.z;
                acc[i][3] += xv[i] * w4.w;
            }
        }
        __syncthreads();
    }

    // store h as fp16 (message values): 2 half2 per thread per row
#pragma unroll
    for (int i = 0; i < 8; i++) {
        int grow = rowBase + ty * 8 + i;
        if (grow < NNODES) {
            __half2 p0 = __floats2half2_rn(acc[i][0], acc[i][1]);
            __half2 p1 = __floats2half2_rn(acc[i][2], acc[i][3]);
            g_hh[(size_t)grow * 32 + tx * 2]     = p0;
            g_hh[(size_t)grow * 32 + tx * 2 + 1] = p1;
        }
    }

    // attention-logit epilogue from fp32 acc: head = tx>>1
    float4 as4 = ((const float4*)att_src)[tx];
    float4 ad4 = ((const float4*)att_dst)[tx];
    int head = tx >> 1;
#pragma unroll
    for (int i = 0; i < 8; i++) {
        float ps = acc[i][0] * as4.x + acc[i][1] * as4.y
                 + acc[i][2] * as4.z + acc[i][3] * as4.w;
        float pd = acc[i][0] * ad4.x + acc[i][1] * ad4.y
                 + acc[i][2] * ad4.z + acc[i][3] * ad4.w;
        ps += __shfl_xor_sync(0xFFFFFFFFu, ps, 1);
        pd += __shfl_xor_sync(0xFFFFFFFFu, pd, 1);
        int grow = rowBase + ty * 8 + i;
        if (!(tx & 1) && grow < NNODES) {
            g_asrc[grow * 8 + head] = ps;
            g_adst[grow * 8 + head] = pd;
        }
    }
}

// ---------------- K5: fused single-pass softmax + aggregate + bias + relu --
// One warp per destination node. Lane l owns channels {2l,2l+1}, head l>>2.
// Messages gathered in fp16 (half L2 traffic); exp weights stay fp32.
__global__ void node_kernel(float* __restrict__ out, const float* __restrict__ bias) {
    int gw = (blockIdx.x * blockDim.x + threadIdx.x) >> 5;
    if (gw >= NNODES) return;
    int lane = threadIdx.x & 31;
    int beg = g_rowptr[gw], end = g_rowptr[gw + 1];
    int hd = lane >> 2;
    float adst = g_adst[gw * 8 + hd];

    // self loop
    float vs = g_asrc[gw * 8 + hd] + adst;
    vs = vs > 0.f ? vs : 0.2f * vs;
    float exs = __expf(vs);
    float2 hs = __half22float2(g_hh[(size_t)gw * 32 + lane]);
    float denom = exs;
    float ax = exs * hs.x, ay = exs * hs.y;

    int j = beg;
    for (; j + 4 <= end; j += 4) {
        int s0 = __ldg(&g_csr_src[j]);
        int s1 = __ldg(&g_csr_src[j + 1]);
        int s2 = __ldg(&g_csr_src[j + 2]);
        int s3 = __ldg(&g_csr_src[j + 3]);
        float e0 = g_asrc[s0 * 8 + hd];
        float e1 = g_asrc[s1 * 8 + hd];
        float e2 = g_asrc[s2 * 8 + hd];
        float e3 = g_asrc[s3 * 8 + hd];
        __half2 q0 = g_hh[(size_t)s0 * 32 + lane];
        __half2 q1 = g_hh[(size_t)s1 * 32 + lane];
        __half2 q2 = g_hh[(size_t)s2 * 32 + lane];
        __half2 q3 = g_hh[(size_t)s3 * 32 + lane];
        float v0 = e0 + adst; v0 = v0 > 0.f ? v0 : 0.2f * v0;
        float v1 = e1 + adst; v1 = v1 > 0.f ? v1 : 0.2f * v1;
        float v2 = e2 + adst; v2 = v2 > 0.f ? v2 : 0.2f * v2;
        float v3 = e3 + adst; v3 = v3 > 0.f ? v3 : 0.2f * v3;
        float x0 = __expf(v0), x1 = __expf(v1), x2 = __expf(v2), x3 = __expf(v3);
        float2 h0 = __half22float2(q0);
        float2 h1 = __half22float2(q1);
        float2 h2v = __half22float2(q2);
        float2 h3 = __half22float2(q3);
        denom += (x0 + x1) + (x2 + x3);
        ax += x0 * h0.x + x1 * h1.x + x2 * h2v.x + x3 * h3.x;
        ay += x0 * h0.y + x1 * h1.y + x2 * h2v.y + x3 * h3.y;
    }
    for (; j < end; j++) {
        int s = __ldg(&g_csr_src[j]);
        float v = g_asrc[s * 8 + hd] + adst;
        v = v > 0.f ? v : 0.2f * v;
        float ex = __expf(v);
        float2 hv = __half22float2(g_hh[(size_t)s * 32 + lane]);
        denom += ex;
        ax += ex * hv.x;
        ay += ex * hv.y;
    }

    float inv = __fdividef(1.f, denom + 1e-16f);
    float2 b = ((const float2*)bias)[lane];
    float ox = ax * inv + b.x, oy = ay * inv + b.y;
    ((float2*)out)[(size_t)gw * 32 + lane] =
        make_float2(ox > 0.f ? ox : 0.f, oy > 0.f ? oy : 0.f);
}

// ---------------- launch ----------------------------------------------------
extern "C" void kernel_launch(void* const* d_in, const int* in_sizes, int n_in,
                              void* d_out, int out_size) {
    const float* x       = (const float*)d_in[0];
    const void*  ei      = d_in[1];
    const float* W       = (const float*)d_in[2];
    const float* att_src = (const float*)d_in[3];
    const float* att_dst = (const float*)d_in[4];
    const float* bias    = (const float*)d_in[5];
    float*       out     = (float*)d_out;

    init_kernel   <<<(NNODES + 255) / 256, 256>>>((const int*)ei);
    hist_kernel   <<<(E0 / 4 + 255) / 256, 256>>>(ei);
    scan_kernel   <<<NB, 256>>>();
    scatter_kernel<<<(E0 / 4 + 255) / 256, 256>>>(ei);
    gemm_kernel   <<<(NNODES + 127) / 128, 256>>>(x, W, att_src, att_dst);
    node_kernel   <<<(NNODES * 32 + 255) / 256, 256>>>(out, bias);
}

// round 10
// speedup vs baseline: 1.0948x; 1.0948x over previous
#include <cuda_runtime.h>

#define NNODES 100000
#define FEAT   128
#define HEADS  8
#define HC     64          // HEADS*CH
#define E0     1600000     // edges in edge_index (self loops handled analytically)
#define NB     391         // ceil(NNODES/256) scan blocks
#define PACK   72          // floats per node: 64 h + 8 a_src (288B = 9 sectors)

// ---------------- scratch (device globals) ---------------------------------
__device__ float g_pack[NNODES * PACK];         // 28.8 MB: h + a_src interleaved
__device__ float g_adst[NNODES * HEADS];        // 3.2 MB
__device__ int   g_cnt[NNODES];                 // in-degree histogram
__device__ int   g_rowptr[NNODES + 1];          // CSR row pointers
__device__ int   g_fill[NNODES];                // scatter cursors
__device__ int   g_bsums[NB];                   // scan block sums
__device__ int   g_csr_src[E0];                 // CSR: src node per edge
__device__ int   g_is64;

// ---------------- K0: zero histogram + detect dtype ------------------------
// int64 values in [0, N) have every odd 32-bit word == 0 (little endian).
__global__ void init_kernel(const int* __restrict__ ei32) {
    int t = blockIdx.x * blockDim.x + threadIdx.x;
    if (t < NNODES) g_cnt[t] = 0;
    if (t == 0) {
        int all_zero = 1;
#pragma unroll
        for (int i = 1; i < 16; i += 2) all_zero &= (ei32[i] == 0);
        g_is64 = all_zero;
    }
}

// ---------------- K1: in-degree histogram (real edges only) ----------------
__global__ void hist_kernel(const void* __restrict__ ei) {
    int e = blockIdx.x * blockDim.x + threadIdx.x;
    if (e >= E0) return;
    int d = g_is64 ? ((const int*)ei)[2 * (E0 + e)]      // low word of int64
                   : ((const int*)ei)[E0 + e];
    atomicAdd(&g_cnt[d], 1);
}

// ---------------- K2a/b/c: exclusive prefix scan of g_cnt (shuffle) --------
__global__ void scanA_kernel() {
    int t = threadIdx.x, i = blockIdx.x * 256 + t;
    int lane = t & 31, w = t >> 5;
    int v = (i < NNODES) ? g_cnt[i] : 0;
    int x = v;
#pragma unroll
    for (int off = 1; off < 32; off <<= 1) {
        int y = __shfl_up_sync(0xFFFFFFFFu, x, off);
        if (lane >= off) x += y;
    }
    __shared__ int wsum[8];
    if (lane == 31) wsum[w] = x;
    __syncthreads();
    if (w == 0 && lane < 8) {
        int y = wsum[lane];
#pragma unroll
        for (int off = 1; off < 8; off <<= 1) {
            int z = __shfl_up_sync(0xFFu, y, off);
            if (lane >= off) y += z;
        }
        wsum[lane] = y;
    }
    __syncthreads();
    int incl = x + (w > 0 ? wsum[w - 1] : 0);
    if (i < NNODES) g_rowptr[i] = incl - v;       // block-local exclusive
    if (t == 255) g_bsums[blockIdx.x] = incl;
}

__global__ void scanB_kernel() {                  // 512 threads, 391 elems
    int t = threadIdx.x, lane = t & 31, w = t >> 5;
    int v = (t < NB) ? g_bsums[t] : 0;
    int x = v;
#pragma unroll
    for (int off = 1; off < 32; off <<= 1) {
        int y = __shfl_up_sync(0xFFFFFFFFu, x, off);
        if (lane >= off) x += y;
    }
    __shared__ int wsum[16];
    if (lane == 31) wsum[w] = x;
    __syncthreads();
    if (w == 0 && lane < 16) {
        int y = wsum[lane];
#pragma unroll
        for (int off = 1; off < 16; off <<= 1) {
            int z = __shfl_up_sync(0xFFFFu, y, off);
            if (lane >= off) y += z;
        }
        wsum[lane] = y;
    }
    __syncthreads();
    int incl = x + (w > 0 ? wsum[w - 1] : 0);
    if (t < NB) g_bsums[t] = incl - v;            // exclusive
}

__global__ void scanC_kernel() {
    int i = blockIdx.x * blockDim.x + threadIdx.x;
    if (i > NNODES) return;
    if (i == NNODES) { g_rowptr[NNODES] = E0; return; }
    int r = g_rowptr[i] + g_bsums[i >> 8];
    g_rowptr[i] = r;
    g_fill[i] = r;
}

// ---------------- K3: scatter edges into CSR -------------------------------
__global__ void scatter_kernel(const void* __restrict__ ei) {
    int e = blockIdx.x * blockDim.x + threadIdx.x;
    if (e >= E0) return;
    int s, d;
    const int* p = (const int*)ei;
    if (g_is64) { s = p[2 * e]; d = p[2 * (E0 + e)]; }
    else        { s = p[e];     d = p[E0 + e]; }
    int pos = atomicAdd(&g_fill[d], 1);
    g_csr_src[pos] = s;
}

// ---------------- K4: h = x @ W (BM=128,BN=64,BK=32, 8x4, reg-prefetch) ----
// Stores h into packed layout (row stride 72 floats).
__global__ void gemm_kernel(const float* __restrict__ x, const float* __restrict__ W) {
    __shared__ __align__(16) float Xs[32][132];    // [k][row] k-major
    __shared__ __align__(16) float Ws[32][64];

    int tid = threadIdx.x;
    int tx = tid & 15;                             // cols tx*4..+3
    int ty = tid >> 4;                             // rows ty*8..+7
    int rowBase = blockIdx.x * 128;

    float acc[8][4];
#pragma unroll
    for (int i = 0; i < 8; i++)
#pragma unroll
        for (int j = 0; j < 4; j++) acc[i][j] = 0.f;

    float4 xr[4], wr[2];
#pragma unroll
    for (int i = 0; i < 4; i++) {
        int idx = tid + i * 256;
        int r = idx >> 3, q = idx & 7;
        int grow = rowBase + r;
        xr[i] = (grow < NNODES)
              ? *(const float4*)(x + (size_t)grow * FEAT + q * 4)
              : make_float4(0.f, 0.f, 0.f, 0.f);
    }
#pragma unroll
    for (int i = 0; i < 2; i++) {
        int idx = tid + i * 256;
        int k = idx >> 4, q = idx & 15;
        wr[i] = *(const float4*)(W + (size_t)k * HC + q * 4);
    }

    for (int kt = 0; kt < 4; kt++) {
#pragma unroll
        for (int i = 0; i < 4; i++) {
            int idx = tid + i * 256;
            int r = idx >> 3, q = idx & 7;
            Xs[q * 4 + 0][r] = xr[i].x; Xs[q * 4 + 1][r] = xr[i].y;
            Xs[q * 4 + 2][r] = xr[i].z; Xs[q * 4 + 3][r] = xr[i].w;
        }
#pragma unroll
        for (int i = 0; i < 2; i++) {
            int idx = tid + i * 256;
            int k = idx >> 4, q = idx & 15;
            *(float4*)&Ws[k][q * 4] = wr[i];
        }
        __syncthreads();
        if (kt < 3) {
#pragma unroll
            for (int i = 0; i < 4; i++) {
                int idx = tid + i * 256;
                int r = idx >> 3, q = idx & 7;
                int grow = rowBase + r;
                xr[i] = (grow < NNODES)
                      ? *(const float4*)(x + (size_t)grow * FEAT + (kt + 1) * 32 + q * 4)
                      : make_float4(0.f, 0.f, 0.f, 0.f);
            }
#pragma unroll
            for (int i = 0; i < 2; i++) {
                int idx = tid + i * 256;
                int k = idx >> 4, q = idx & 15;
                wr[i] = *(const float4*)(W + (size_t)((kt + 1) * 32 + k) * HC + q * 4);
            }
        }
#pragma unroll
        for (int kk = 0; kk < 32; kk++) {
            float4 w4  = *(float4*)&Ws[kk][tx * 4];
            float4 xlo = *(float4*)&Xs[kk][ty * 8];
            float4 xhi = *(float4*)&Xs[kk][ty * 8 + 4];
            float xv[8] = {xlo.x, xlo.y, xlo.z, xlo.w, xhi.x, xhi.y, xhi.z, xhi.w};
#pragma unroll
            for (int i = 0; i < 8; i++) {
                acc[i][0] += xv[i] * w4.x;
                acc[i][1] += xv[i] * w4.y;
                acc[i][2] += xv[i] * w4.z;
                acc[i][3] += xv[i] * w4.w;
            }
        }
        __syncthreads();
    }
#pragma unroll
    for (int i = 0; i < 8; i++) {
        int grow = rowBase + ty * 8 + i;
        if (grow < NNODES) {
            float4 v = make_float4(acc[i][0], acc[i][1], acc[i][2], acc[i][3]);
            *(float4*)(g_pack + (size_t)grow * PACK + tx * 4) = v;
        }
    }
}

// ---------------- K5: attention logits; a_src goes INTO the packed row -----
__global__ void att_kernel(const float* __restrict__ att_src,
                           const float* __restrict__ att_dst) {
    int t = blockIdx.x * blockDim.x + threadIdx.x;
    if (t >= NNODES * HEADS) return;
    int n = t >> 3, hd = t & 7;
    const float4* h4 = (const float4*)(g_pack + (size_t)n * PACK);
    float4 a = h4[hd * 2];
    float4 b = h4[hd * 2 + 1];
    float4 s0 = ((const float4*)att_src)[hd * 2];
    float4 s1 = ((const float4*)att_src)[hd * 2 + 1];
    float4 d0 = ((const float4*)att_dst)[hd * 2];
    float4 d1 = ((const float4*)att_dst)[hd * 2 + 1];
    g_pack[(size_t)n * PACK + 64 + hd] =
          a.x * s0.x + a.y * s0.y + a.z * s0.z + a.w * s0.w
        + b.x * s1.x + b.y * s1.y + b.z * s1.z + b.w * s1.w;
    g_adst[t] = a.x * d0.x + a.y * d0.y + a.z * d0.z + a.w * d0.w
              + b.x * d1.x + b.y * d1.y + b.z * d1.z + b.w * d1.w;
}

// ---------------- K6: fused single-pass softmax + aggregate + bias + relu --
// One warp per destination node. Lane l owns channels {2l,2l+1}, head l>>2.
// Per edge the warp touches ONE contiguous 288B row: 8 h sectors + 1 a_src
// sector (vs 8+8 scattered before) — L1tex wavefront count nearly halved.
// out = (sum ex_j h_j)/(sum ex_j + eps); shift-free exp validated (2e-7).
__global__ void node_kernel(float* __restrict__ out, const float* __restrict__ bias) {
    int gw = (blockIdx.x * blockDim.x + threadIdx.x) >> 5;
    if (gw >= NNODES) return;
    int lane = threadIdx.x & 31;
    int beg = g_rowptr[gw], end = g_rowptr[gw + 1];
    int hd = lane >> 2;
    float adst = g_adst[gw * 8 + hd];

    // self loop
    const float* prow = g_pack + (size_t)gw * PACK;
    float vs = prow[64 + hd] + adst;
    vs = vs > 0.f ? vs : 0.2f * vs;
    float exs = __expf(vs);
    float2 hs = ((const float2*)prow)[lane];
    float denom = exs;
    float ax = exs * hs.x, ay = exs * hs.y;

    int j = beg;
    for (; j + 4 <= end; j += 4) {
        int s0 = __ldg(&g_csr_src[j]);
        int s1 = __ldg(&g_csr_src[j + 1]);
        int s2 = __ldg(&g_csr_src[j + 2]);
        int s3 = __ldg(&g_csr_src[j + 3]);
        const float* p0 = g_pack + (size_t)s0 * PACK;
        const float* p1 = g_pack + (size_t)s1 * PACK;
        const float* p2 = g_pack + (size_t)s2 * PACK;
        const float* p3 = g_pack + (size_t)s3 * PACK;
        float e0 = p0[64 + hd];
        float e1 = p1[64 + hd];
        float e2 = p2[64 + hd];
        float e3 = p3[64 + hd];
        float2 h0 = ((const float2*)p0)[lane];
        float2 h1 = ((const float2*)p1)[lane];
        float2 h2v = ((const float2*)p2)[lane];
        float2 h3 = ((const float2*)p3)[lane];
        float v0 = e0 + adst; v0 = v0 > 0.f ? v0 : 0.2f * v0;
        float v1 = e1 + adst; v1 = v1 > 0.f ? v1 : 0.2f * v1;
        float v2 = e2 + adst; v2 = v2 > 0.f ? v2 : 0.2f * v2;
        float v3 = e3 + adst; v3 = v3 > 0.f ? v3 : 0.2f * v3;
        float x0 = __expf(v0), x1 = __expf(v1), x2 = __expf(v2), x3 = __expf(v3);
        denom += (x0 + x1) + (x2 + x3);
        ax += x0 * h0.x + x1 * h1.x + x2 * h2v.x + x3 * h3.x;
        ay += x0 * h0.y + x1 * h1.y + x2 * h2v.y + x3 * h3.y;
    }
    for (; j < end; j++) {
        int s = __ldg(&g_csr_src[j]);
        const float* p = g_pack + (size_t)s * PACK;
        float v = p[64 + hd] + adst;
        v = v > 0.f ? v : 0.2f * v;
        float ex = __expf(v);
        float2 hv = ((const float2*)p)[lane];
        denom += ex;
        ax += ex * hv.x;
        ay += ex * hv.y;
    }

    float inv = __fdividef(1.f, denom + 1e-16f);
    float2 b = ((const float2*)bias)[lane];
    float ox = ax * inv + b.x, oy = ay * inv + b.y;
    ((float2*)out)[(size_t)gw * 32 + lane] =
        make_float2(ox > 0.f ? ox : 0.f, oy > 0.f ? oy : 0.f);
}

// ---------------- launch ----------------------------------------------------
// gemm placed 4th so the profiler's fixed sampling window captures it.
extern "C" void kernel_launch(void* const* d_in, const int* in_sizes, int n_in,
                              void* d_out, int out_size) {
    const float* x       = (const float*)d_in[0];
    const void*  ei      = d_in[1];
    const float* W       = (const float*)d_in[2];
    const float* att_src = (const float*)d_in[3];
    const float* att_dst = (const float*)d_in[4];
    const float* bias    = (const float*)d_in[5];
    float*       out     = (float*)d_out;

    init_kernel   <<<(NNODES + 255) / 256, 256>>>((const int*)ei);
    hist_kernel   <<<(E0 + 255) / 256, 256>>>(ei);
    scanA_kernel  <<<NB, 256>>>();
    gemm_kernel   <<<(NNODES + 127) / 128, 256>>>(x, W);
    scanB_kernel  <<<1, 512>>>();
    scanC_kernel  <<<(NNODES + 1 + 255) / 256, 256>>>();
    scatter_kernel<<<(E0 + 255) / 256, 256>>>(ei);
    att_kernel    <<<(NNODES * HEADS + 255) / 256, 256>>>(att_src, att_dst);
    node_kernel   <<<(NNODES * 32 + 255) / 256, 256>>>(out, bias);
}

// round 13
// speedup vs baseline: 1.1408x; 1.0420x over previous
#include <cuda_runtime.h>
#include <cuda_fp16.h>

#define NNODES 100000
#define FEAT   128
#define HEADS  8
#define HC     64          // HEADS*CH
#define E0     1600000     // edges in edge_index (self loops handled analytically)
#define NB     391         // ceil(NNODES/256) scan blocks
#define PACKW  40          // 32-bit words per node: 32 (64 fp16 h) + 8 (fp32 a_src)

// ---------------- scratch (device globals) ---------------------------------
__device__ unsigned int g_pack[NNODES * PACKW]; // 16 MB: fp16 h + fp32 a_src
__device__ float g_adst[NNODES * HEADS];        // 3.2 MB
__device__ int   g_cnt[NNODES];                 // in-degree histogram
__device__ int   g_rowptr[NNODES + 1];          // CSR row pointers
__device__ int   g_fill[NNODES];                // scatter cursors
__device__ int   g_bsums[NB];                   // scan block sums
__device__ int   g_csr_src[E0];                 // CSR: src node per edge
__device__ int   g_is64;

// ---------------- K0: zero histogram + detect dtype ------------------------
// int64 values in [0, N) have every odd 32-bit word == 0 (little endian).
__global__ void init_kernel(const int* __restrict__ ei32) {
    int t = blockIdx.x * blockDim.x + threadIdx.x;
    if (t < NNODES) g_cnt[t] = 0;
    if (t == 0) {
        int all_zero = 1;
#pragma unroll
        for (int i = 1; i < 16; i += 2) all_zero &= (ei32[i] == 0);
        g_is64 = all_zero;
    }
}

// ---------------- K1: in-degree histogram (real edges only) ----------------
__global__ void hist_kernel(const void* __restrict__ ei) {
    int e = blockIdx.x * blockDim.x + threadIdx.x;
    if (e >= E0) return;
    int d = g_is64 ? ((const int*)ei)[2 * (E0 + e)]      // low word of int64
                   : ((const int*)ei)[E0 + e];
    atomicAdd(&g_cnt[d], 1);
}

// ---------------- K2a/b/c: exclusive prefix scan of g_cnt (shuffle) --------
__global__ void scanA_kernel() {
    int t = threadIdx.x, i = blockIdx.x * 256 + t;
    int lane = t & 31, w = t >> 5;
    int v = (i < NNODES) ? g_cnt[i] : 0;
    int x = v;
#pragma unroll
    for (int off = 1; off < 32; off <<= 1) {
        int y = __shfl_up_sync(0xFFFFFFFFu, x, off);
        if (lane >= off) x += y;
    }
    __shared__ int wsum[8];
    if (lane == 31) wsum[w] = x;
    __syncthreads();
    if (w == 0 && lane < 8) {
        int y = wsum[lane];
#pragma unroll
        for (int off = 1; off < 8; off <<= 1) {
            int z = __shfl_up_sync(0xFFu, y, off);
            if (lane >= off) y += z;
        }
        wsum[lane] = y;
    }
    __syncthreads();
    int incl = x + (w > 0 ? wsum[w - 1] : 0);
    if (i < NNODES) g_rowptr[i] = incl - v;       // block-local exclusive
    if (t == 255) g_bsums[blockIdx.x] = incl;
}

__global__ void scanB_kernel() {                  // 512 threads, 391 elems
    int t = threadIdx.x, lane = t & 31, w = t >> 5;
    int v = (t < NB) ? g_bsums[t] : 0;
    int x = v;
#pragma unroll
    for (int off = 1; off < 32; off <<= 1) {
        int y = __shfl_up_sync(0xFFFFFFFFu, x, off);
        if (lane >= off) x += y;
    }
    __shared__ int wsum[16];
    if (lane == 31) wsum[w] = x;
    __syncthreads();
    if (w == 0 && lane < 16) {
        int y = wsum[lane];
#pragma unroll
        for (int off = 1; off < 16; off <<= 1) {
            int z = __shfl_up_sync(0xFFFFu, y, off);
            if (lane >= off) y += z;
        }
        wsum[lane] = y;
    }
    __syncthreads();
    int incl = x + (w > 0 ? wsum[w - 1] : 0);
    if (t < NB) g_bsums[t] = incl - v;            // exclusive
}

__global__ void scanC_kernel() {
    int i = blockIdx.x * blockDim.x + threadIdx.x;
    if (i > NNODES) return;
    if (i == NNODES) { g_rowptr[NNODES] = E0; return; }
    int r = g_rowptr[i] + g_bsums[i >> 8];
    g_rowptr[i] = r;
    g_fill[i] = r;
}

// ---------------- K3: scatter edges into CSR -------------------------------
__global__ void scatter_kernel(const void* __restrict__ ei) {
    int e = blockIdx.x * blockDim.x + threadIdx.x;
    if (e >= E0) return;
    int s, d;
    const int* p = (const int*)ei;
    if (g_is64) { s = p[2 * e]; d = p[2 * (E0 + e)]; }
    else        { s = p[e];     d = p[E0 + e]; }
    int pos = atomicAdd(&g_fill[d], 1);
    g_csr_src[pos] = s;
}

// ---------------- K4: h = x @ W + fused logit epilogue, h stored fp16 ------
// BM=128, BN=64, BK=32, 8x4 microtile, register prefetch (R10 scalar core).
// Logits ps/pd computed from fp32 register accumulators (+shfl_xor(1));
// only the linearly-entering message values h are quantized to fp16.
__global__ void gemm_kernel(const float* __restrict__ x, const float* __restrict__ W,
                            const float* __restrict__ att_src,
                            const float* __restrict__ att_dst) {
    __shared__ __align__(16) float Xs[32][132];    // [k][row] k-major
    __shared__ __align__(16) float Ws[32][64];

    int tid = threadIdx.x;
    int tx = tid & 15;                             // cols tx*4..+3
    int ty = tid >> 4;                             // rows ty*8..+7
    int rowBase = blockIdx.x * 128;

    float acc[8][4];
#pragma unroll
    for (int i = 0; i < 8; i++)
#pragma unroll
        for (int j = 0; j < 4; j++) acc[i][j] = 0.f;

    float4 xr[4], wr[2];
#pragma unroll
    for (int i = 0; i < 4; i++) {
        int idx = tid + i * 256;
        int r = idx >> 3, q = idx & 7;
        int grow = rowBase + r;
        xr[i] = (grow < NNODES)
              ? *(const float4*)(x + (size_t)grow * FEAT + q * 4)
              : make_float4(0.f, 0.f, 0.f, 0.f);
    }
#pragma unroll
    for (int i = 0; i < 2; i++) {
        int idx = tid + i * 256;
        int k = idx >> 4, q = idx & 15;
        wr[i] = *(const float4*)(W + (size_t)k * HC + q * 4);
    }

    for (int kt = 0; kt < 4; kt++) {
#pragma unroll
        for (int i = 0; i < 4; i++) {
            int idx = tid + i * 256;
            int r = idx >> 3, q = idx & 7;
            Xs[q * 4 + 0][r] = xr[i].x; Xs[q * 4 + 1][r] = xr[i].y;
            Xs[q * 4 + 2][r] = xr[i].z; Xs[q * 4 + 3][r] = xr[i].w;
        }
#pragma unroll
        for (int i = 0; i < 2; i++) {
            int idx = tid + i * 256;
            int k = idx >> 4, q = idx & 15;
            *(float4*)&Ws[k][q * 4] = wr[i];
        }
        __syncthreads();
        if (kt < 3) {
#pragma unroll
            for (int i = 0; i < 4; i++) {
                int idx = tid + i * 256;
                int r = idx >> 3, q = idx & 7;
                int grow = rowBase + r;
                xr[i] = (grow < NNODES)
                      ? *(const float4*)(x + (size_t)grow * FEAT + (kt + 1) * 32 + q * 4)
                      : make_float4(0.f, 0.f, 0.f, 0.f);
            }
#pragma unroll
            for (int i = 0; i < 2; i++) {
                int idx = tid + i * 256;
                int k = idx >> 4, q = idx & 15;
                wr[i] = *(const float4*)(W + (size_t)((kt + 1) * 32 + k) * HC + q * 4);
            }
        }
#pragma unroll
        for (int kk = 0; kk < 32; kk++) {
            float4 w4  = *(float4*)&Ws[kk][tx * 4];
            float4 xlo = *(float4*)&Xs[kk][ty * 8];
            float4 xhi = *(float4*)&Xs[kk][ty * 8 + 4];
            float xv[8] = {xlo.x, xlo.y, xlo.z, xlo.w, xhi.x, xhi.y, xhi.z, xhi.w};
#pragma unroll
            for (int i = 0; i < 8; i++) {
                acc[i][0] += xv[i] * w4.x;
                acc[i][1] += xv[i] * w4.y;
                acc[i][2] += xv[i] * w4.z;
                acc[i][3] += xv[i] * w4.w;
            }
        }
        __syncthreads();
    }

    // store h as fp16 into packed row (words [0..31], 2 words per thread)
#pragma unroll
    for (int i = 0; i < 8; i++) {
        int grow = rowBase + ty * 8 + i;
        if (grow < NNODES) {
            __half2 p0 = __floats2half2_rn(acc[i][0], acc[i][1]);
            __half2 p1 = __floats2half2_rn(acc[i][2], acc[i][3]);
            unsigned int u0 = *(unsigned int*)&p0;
            unsigned int u1 = *(unsigned int*)&p1;
            *(uint2*)(g_pack + (size_t)grow * PACKW + tx * 2) = make_uint2(u0, u1);
        }
    }

    // fused fp32 logit epilogue: head = tx>>1; shfl_xor(1) combines col pairs
    float4 as4 = ((const float4*)att_src)[tx];
    float4 ad4 = ((const float4*)att_dst)[tx];
    int head = tx >> 1;
#pragma unroll
    for (int i = 0; i < 8; i++) {
        float ps = acc[i][0] * as4.x + acc[i][1] * as4.y
                 + acc[i][2] * as4.z + acc[i][3] * as4.w;
        float pd = acc[i][0] * ad4.x + acc[i][1] * ad4.y
                 + acc[i][2] * ad4.z + acc[i][3] * ad4.w;
        ps += __shfl_xor_sync(0xFFFFFFFFu, ps, 1);
        pd += __shfl_xor_sync(0xFFFFFFFFu, pd, 1);
        int grow = rowBase + ty * 8 + i;
        if (!(tx & 1) && grow < NNODES) {
            g_pack[(size_t)grow * PACKW + 32 + head] = __float_as_uint(ps);
            g_adst[grow * 8 + head] = pd;
        }
    }
}

// ---------------- K5: fused single-pass softmax + aggregate + bias + relu --
// One warp per destination node. Lane l owns channels {2l,2l+1}, head l>>2.
// Per edge the warp touches ONE 160B row: 4 sectors fp16 h + 1 sector a_src
// (vs 9 sectors in the fp32 layout). Logits fp32; messages fp16 (error class
// validated R9: rel_err 1.9e-4). out = (sum ex_j h_j)/(sum ex_j + eps).
__global__ void node_kernel(float* __restrict__ out, const float* __restrict__ bias) {
    int gw = (blockIdx.x * blockDim.x + threadIdx.x) >> 5;
    if (gw >= NNODES) return;
    int lane = threadIdx.x & 31;
    int beg = g_rowptr[gw], end = g_rowptr[gw + 1];
    int hd = lane >> 2;
    float adst = g_adst[gw * 8 + hd];

    // self loop
    const unsigned int* prow = g_pack + (size_t)gw * PACKW;
    float vs = __uint_as_float(prow[32 + hd]) + adst;
    vs = vs > 0.f ? vs : 0.2f * vs;
    float exs = __expf(vs);
    float2 hs = __half22float2(*(const __half2*)(prow + lane));
    float denom = exs;
    float ax = exs * hs.x, ay = exs * hs.y;

    int j = beg;
    for (; j + 4 <= end; j += 4) {
        int s0 = __ldg(&g_csr_src[j]);
        int s1 = __ldg(&g_csr_src[j + 1]);
        int s2 = __ldg(&g_csr_src[j + 2]);
        int s3 = __ldg(&g_csr_src[j + 3]);
        const unsigned int* p0 = g_pack + (size_t)s0 * PACKW;
        const unsigned int* p1 = g_pack + (size_t)s1 * PACKW;
        const unsigned int* p2 = g_pack + (size_t)s2 * PACKW;
        const unsigned int* p3 = g_pack + (size_t)s3 * PACKW;
        float e0 = __uint_as_float(p0[32 + hd]);
        float e1 = __uint_as_float(p1[32 + hd]);
        float e2 = __uint_as_float(p2[32 + hd]);
        float e3 = __uint_as_float(p3[32 + hd]);
        __half2 q0 = *(const __half2*)(p0 + lane);
        __half2 q1 = *(const __half2*)(p1 + lane);
        __half2 q2 = *(const __half2*)(p2 + lane);
        __half2 q3 = *(const __half2*)(p3 + lane);
        float v0 = e0 + adst; v0 = v0 > 0.f ? v0 : 0.2f * v0;
        float v1 = e1 + adst; v1 = v1 > 0.f ? v1 : 0.2f * v1;
        float v2 = e2 + adst; v2 = v2 > 0.f ? v2 : 0.2f * v2;
        float v3 = e3 + adst; v3 = v3 > 0.f ? v3 : 0.2f * v3;
        float x0 = __expf(v0), x1 = __expf(v1), x2 = __expf(v2), x3 = __expf(v3);
        float2 h0 = __half22float2(q0);
        float2 h1 = __half22float2(q1);
        float2 h2v = __half22float2(q2);
        float2 h3 = __half22float2(q3);
        denom += (x0 + x1) + (x2 + x3);
        ax += x0 * h0.x + x1 * h1.x + x2 * h2v.x + x3 * h3.x;
        ay += x0 * h0.y + x1 * h1.y + x2 * h2v.y + x3 * h3.y;
    }
    for (; j < end; j++) {
        int s = __ldg(&g_csr_src[j]);
        const unsigned int* p = g_pack + (size_t)s * PACKW;
        float v = __uint_as_float(p[32 + hd]) + adst;
        v = v > 0.f ? v : 0.2f * v;
        float ex = __expf(v);
        float2 hv = __half22float2(*(const __half2*)(p + lane));
        denom += ex;
        ax += ex * hv.x;
        ay += ex * hv.y;
    }

    float inv = __fdividef(1.f, denom + 1e-16f);
    float2 b = ((const float2*)bias)[lane];
    float ox = ax * inv + b.x, oy = ay * inv + b.y;
    ((float2*)out)[(size_t)gw * 32 + lane] =
        make_float2(ox > 0.f ? ox : 0.f, oy > 0.f ? oy : 0.f);
}

// ---------------- launch ----------------------------------------------------
// gemm placed 4th so the profiler's fixed sampling window captures it.
extern "C" void kernel_launch(void* const* d_in, const int* in_sizes, int n_in,
                              void* d_out, int out_size) {
    const float* x       = (const float*)d_in[0];
    const void*  ei      = d_in[1];
    const float* W       = (const float*)d_in[2];
    const float* att_src = (const float*)d_in[3];
    const float* att_dst = (const float*)d_in[4];
    const float* bias    = (const float*)d_in[5];
    float*       out     = (float*)d_out;

    init_kernel   <<<(NNODES + 255) / 256, 256>>>((const int*)ei);
    hist_kernel   <<<(E0 + 255) / 256, 256>>>(ei);
    scanA_kernel  <<<NB, 256>>>();
    gemm_kernel   <<<(NNODES + 127) / 128, 256>>>(x, W, att_src, att_dst);
    scanB_kernel  <<<1, 512>>>();
    scanC_kernel  <<<(NNODES + 1 + 255) / 256, 256>>>();
    scatter_kernel<<<(E0 + 255) / 256, 256>>>(ei);
    node_kernel   <<<(NNODES * 32 + 255) / 256, 256>>>(out, bias);
}